// round 1
// baseline (speedup 1.0000x reference)
#include <cuda_runtime.h>
#include <math.h>

#define B_  1024
#define M_  65536
#define D_  384
#define H_  384
#define K_  5
#define MS_ 16            // M splits for the main kernel
#define QT  64            // queries per CTA
#define MT  128           // m rows per tile
#define KC  32            // k chunk
#define QTP 68            // padded q tile stride (mult of 4, !=0 mod 32)
#define MTP 132           // padded m tile stride
#define MCHUNK (M_/MS_)   // 4096
#define NTILES (MCHUNK/MT) // 32

// ---------------- scratch (device globals; no allocation) ----------------
__device__ float g_center[2];
__device__ float g_act[M_];
__device__ float g_rm[M_];
__device__ float g_rq[B_];
__device__ float g_candv[B_ * MS_ * K_];
__device__ int   g_candi[B_ * MS_ * K_];
__device__ int   g_topk[B_ * K_];
__device__ float g_xproj[B_ * 6 * H_];
__device__ float g_gate[B_ * H_];
__device__ float g_hbuf[2][B_ * H_];

// ---------------- kernel 1: center of spatial_weights ----------------
__global__ void k_center(const float* __restrict__ sw) {
    __shared__ float s0[128], s1[128];
    int i = threadIdx.x;
    float a = 0.f, b = 0.f;
    for (int j = i; j < H_; j += 128) { a += sw[j * 2]; b += sw[j * 2 + 1]; }
    s0[i] = a; s1[i] = b;
    __syncthreads();
    for (int off = 64; off > 0; off >>= 1) {
        if (i < off) { s0[i] += s0[i + off]; s1[i] += s1[i + off]; }
        __syncthreads();
    }
    if (i == 0) { g_center[0] = s0[0] / (float)H_; g_center[1] = s1[0] / (float)H_; }
}

// ---------------- kernel 2: per-row stats (warp per row) ----------------
__global__ void k_prep(const float* __restrict__ query,
                       const float* __restrict__ mem,
                       const float* __restrict__ coords) {
    int w = (blockIdx.x * blockDim.x + threadIdx.x) >> 5;
    int lane = threadIdx.x & 31;
    if (w < M_) {
        const float* row = mem + (size_t)w * D_;
        float ss = 0.f;
        #pragma unroll
        for (int j = 0; j < D_ / 32; j++) { float v = row[lane + j * 32]; ss += v * v; }
        #pragma unroll
        for (int o = 16; o; o >>= 1) ss += __shfl_xor_sync(0xffffffffu, ss, o);
        if (lane == 0) {
            g_rm[w] = 1.f / sqrtf(ss);
            float dx = coords[2 * w]     - g_center[0];
            float dy = coords[2 * w + 1] - g_center[1];
            g_act[w] = 1.f / (1.f + sqrtf(dx * dx + dy * dy));
        }
    } else if (w < M_ + B_) {
        int b = w - M_;
        const float* row = query + (size_t)b * D_;
        float ss = 0.f;
        #pragma unroll
        for (int j = 0; j < D_ / 32; j++) { float v = row[lane + j * 32]; ss += v * v; }
        #pragma unroll
        for (int o = 16; o; o >>= 1) ss += __shfl_xor_sync(0xffffffffu, ss, o);
        if (lane == 0) g_rq[b] = 1.f / sqrtf(ss);
    }
}

// ---------------- kernel 3: fused GEMM + per-split top-5 ----------------
__global__ void __launch_bounds__(256, 1)
k_main(const float* __restrict__ query, const float* __restrict__ mem) {
    extern __shared__ float smem[];
    float* q_s = smem;                  // [D_][QTP]
    float* m_s = smem + D_ * QTP;       // [KC][MTP]

    int tid = threadIdx.x;
    int tx = tid & 15, ty = tid >> 4;   // tx -> m, ty -> q
    int qb = blockIdx.y * QT;
    int mbase0 = blockIdx.x * MCHUNK;

    // load query tile transposed
    for (int idx = tid; idx < QT * D_; idx += 256) {
        int q = idx / D_;
        int k = idx - q * D_;
        q_s[k * QTP + q] = query[(size_t)(qb + q) * D_ + k];
    }

    float rq[4];
    #pragma unroll
    for (int i = 0; i < 4; i++) rq[i] = g_rq[qb + ty * 4 + i];

    float tv[4][K_];
    int   tix[4][K_];
    #pragma unroll
    for (int i = 0; i < 4; i++)
        #pragma unroll
        for (int s = 0; s < K_; s++) { tv[i][s] = -3.4e38f; tix[i][s] = 0; }

    __syncthreads();

    for (int mt = 0; mt < NTILES; mt++) {
        int mg = mbase0 + mt * MT;
        float acc[4][8];
        #pragma unroll
        for (int i = 0; i < 4; i++)
            #pragma unroll
            for (int j = 0; j < 8; j++) acc[i][j] = 0.f;

        for (int kc = 0; kc < D_; kc += KC) {
            __syncthreads();
            // stage 128 m-rows x 32 k, transposed
            #pragma unroll
            for (int l = 0; l < 4; l++) {
                int idx = tid + l * 256;          // 1024 float4 units
                int m  = idx >> 3;
                int k4 = idx & 7;
                float4 v = *(const float4*)(mem + (size_t)(mg + m) * D_ + kc + k4 * 4);
                int kl = k4 * 4;
                m_s[(kl + 0) * MTP + m] = v.x;
                m_s[(kl + 1) * MTP + m] = v.y;
                m_s[(kl + 2) * MTP + m] = v.z;
                m_s[(kl + 3) * MTP + m] = v.w;
            }
            __syncthreads();

            #pragma unroll 8
            for (int k = 0; k < KC; k++) {
                float4 av  = *(const float4*)(q_s + (kc + k) * QTP + ty * 4);
                float4 b0v = *(const float4*)(m_s + k * MTP + tx * 8);
                float4 b1v = *(const float4*)(m_s + k * MTP + tx * 8 + 4);
                float a[4]  = {av.x, av.y, av.z, av.w};
                float bb[8] = {b0v.x, b0v.y, b0v.z, b0v.w, b1v.x, b1v.y, b1v.z, b1v.w};
                #pragma unroll
                for (int i = 0; i < 4; i++)
                    #pragma unroll
                    for (int j = 0; j < 8; j++)
                        acc[i][j] = fmaf(a[i], bb[j], acc[i][j]);
            }
        }

        // epilogue: similarity + spatial activation, top-5 update
        #pragma unroll
        for (int j = 0; j < 8; j++) {
            int m = mg + tx * 8 + j;
            float rm  = g_rm[m];
            float act = g_act[m];
            #pragma unroll
            for (int i = 0; i < 4; i++) {
                float sc = fminf(rq[i] * rm, 1e8f);   // 1/max(qn*mn, 1e-8)
                float v = fmaf(acc[i][j], sc, act);
                if (v > tv[i][K_ - 1]) {
                    float cv = v; int ci = m;
                    #pragma unroll
                    for (int s = 0; s < K_; s++) {
                        bool gt = cv > tv[i][s];
                        float ov = tv[i][s]; int oi = tix[i][s];
                        tv[i][s]  = gt ? cv : ov;
                        tix[i][s] = gt ? ci : oi;
                        cv = gt ? ov : cv;
                        ci = gt ? oi : ci;
                    }
                }
            }
        }
    }

    // cross-thread merge (16 tx threads per query)
    __syncthreads();
    float* red_v = smem;                              // [QT][16][K_]
    int*   red_i = (int*)(smem + QT * 16 * K_);
    #pragma unroll
    for (int i = 0; i < 4; i++) {
        int ql = ty * 4 + i;
        #pragma unroll
        for (int s = 0; s < K_; s++) {
            red_v[ql * (16 * K_) + tx * K_ + s] = tv[i][s];
            red_i[ql * (16 * K_) + tx * K_ + s] = tix[i][s];
        }
    }
    __syncthreads();
    if (tid < QT) {
        float bv[K_]; int bi[K_];
        #pragma unroll
        for (int s = 0; s < K_; s++) { bv[s] = -3.4e38f; bi[s] = 0; }
        for (int c = 0; c < 16 * K_; c++) {
            float v = red_v[tid * (16 * K_) + c];
            int  ix = red_i[tid * (16 * K_) + c];
            if (v > bv[K_ - 1]) {
                float cv = v; int ci = ix;
                #pragma unroll
                for (int s = 0; s < K_; s++) {
                    bool gt = cv > bv[s];
                    float ov = bv[s]; int oi = bi[s];
                    bv[s] = gt ? cv : ov; bi[s] = gt ? ci : oi;
                    cv = gt ? ov : cv;    ci = gt ? oi : ci;
                }
            }
        }
        int b = qb + tid;
        #pragma unroll
        for (int s = 0; s < K_; s++) {
            g_candv[(size_t)b * (MS_ * K_) + blockIdx.x * K_ + s] = bv[s];
            g_candi[(size_t)b * (MS_ * K_) + blockIdx.x * K_ + s] = bi[s];
        }
    }
}

// ---------------- kernel 4: merge splits -> final top-5 ----------------
__global__ void k_topkfinal() {
    int b = blockIdx.x * blockDim.x + threadIdx.x;
    if (b >= B_) return;
    float bv[K_]; int bi[K_];
    #pragma unroll
    for (int s = 0; s < K_; s++) { bv[s] = -3.4e38f; bi[s] = 0; }
    for (int c = 0; c < MS_ * K_; c++) {
        float v = g_candv[(size_t)b * (MS_ * K_) + c];
        int  ix = g_candi[(size_t)b * (MS_ * K_) + c];
        if (v > bv[K_ - 1]) {
            float cv = v; int ci = ix;
            #pragma unroll
            for (int s = 0; s < K_; s++) {
                bool gt = cv > bv[s];
                float ov = bv[s]; int oi = bi[s];
                bv[s] = gt ? cv : ov; bi[s] = gt ? ci : oi;
                cv = gt ? ov : cv;    ci = gt ? oi : ci;
            }
        }
    }
    #pragma unroll
    for (int s = 0; s < K_; s++) g_topk[b * K_ + s] = bi[s];
}

// ---------------- kernel 5: unified tiled GEMM (xproj / gate / rnn) ----------------
// mode 0: xproj  (rows = 6144 gathered from query/retrieved, W_ih, out=g_xproj)
// mode 1: gate   (rows = 1024 query, W_g, sigmoid, out=g_gate)
// mode 2: rnn    (rows = 1024 h[inbuf], W_hh, + xproj[:,t,:], tanh, out=h[outbuf])
#define GBM 64
#define GBN 128
__global__ void __launch_bounds__(256)
k_gemm(int mode, int t, int inbuf, int outbuf,
       const float* __restrict__ W, const float* __restrict__ bias,
       const float* __restrict__ query, const float* __restrict__ mem) {
    __shared__ __align__(16) float a_s[KC * QTP];
    __shared__ __align__(16) float w_s[KC * MTP];
    int tid = threadIdx.x;
    int tx = tid & 15, ty = tid >> 4;
    int rb = blockIdx.x * GBM;
    int hb = blockIdx.y * GBN;

    float acc[4][8];
    #pragma unroll
    for (int i = 0; i < 4; i++)
        #pragma unroll
        for (int j = 0; j < 8; j++) acc[i][j] = 0.f;

    const float* Abase = (mode == 1) ? query : (mode == 2 ? g_hbuf[inbuf] : nullptr);

    for (int kc = 0; kc < D_; kc += KC) {
        __syncthreads();
        // rows tile (64 x 32), transposed
        #pragma unroll
        for (int l = 0; l < 2; l++) {
            int idx = tid + l * 256;
            int row = idx >> 3, k4 = idx & 7;
            int r = rb + row;
            const float* src;
            if (mode == 0) {
                int bq = r / 6;
                int tt = r - bq * 6;
                src = (tt == 0) ? (query + (size_t)bq * D_)
                                : (mem + (size_t)g_topk[bq * K_ + tt - 1] * D_);
            } else {
                src = Abase + (size_t)r * D_;
            }
            float4 v = *(const float4*)(src + kc + k4 * 4);
            int kl = k4 * 4;
            a_s[(kl + 0) * QTP + row] = v.x;
            a_s[(kl + 1) * QTP + row] = v.y;
            a_s[(kl + 2) * QTP + row] = v.z;
            a_s[(kl + 3) * QTP + row] = v.w;
        }
        // W tile (128 x 32), transposed
        #pragma unroll
        for (int l = 0; l < 4; l++) {
            int idx = tid + l * 256;
            int h = idx >> 3, k4 = idx & 7;
            float4 v = *(const float4*)(W + (size_t)(hb + h) * D_ + kc + k4 * 4);
            int kl = k4 * 4;
            w_s[(kl + 0) * MTP + h] = v.x;
            w_s[(kl + 1) * MTP + h] = v.y;
            w_s[(kl + 2) * MTP + h] = v.z;
            w_s[(kl + 3) * MTP + h] = v.w;
        }
        __syncthreads();

        #pragma unroll 8
        for (int k = 0; k < KC; k++) {
            float4 av  = *(const float4*)(a_s + k * QTP + ty * 4);
            float4 b0v = *(const float4*)(w_s + k * MTP + tx * 8);
            float4 b1v = *(const float4*)(w_s + k * MTP + tx * 8 + 4);
            float a[4]  = {av.x, av.y, av.z, av.w};
            float bb[8] = {b0v.x, b0v.y, b0v.z, b0v.w, b1v.x, b1v.y, b1v.z, b1v.w};
            #pragma unroll
            for (int i = 0; i < 4; i++)
                #pragma unroll
                for (int j = 0; j < 8; j++)
                    acc[i][j] = fmaf(a[i], bb[j], acc[i][j]);
        }
    }

    float* out = (mode == 0) ? g_xproj : (mode == 1 ? g_gate : g_hbuf[outbuf]);
    #pragma unroll
    for (int i = 0; i < 4; i++) {
        int r = rb + ty * 4 + i;
        #pragma unroll
        for (int j = 0; j < 8; j++) {
            int h = hb + tx * 8 + j;
            float v = acc[i][j] + bias[h];
            if (mode == 2) {
                v += g_xproj[(size_t)(r * 6 + t) * H_ + h];
                v = tanhf(v);
            } else if (mode == 1) {
                v = 1.f / (1.f + expf(-v));
            }
            out[(size_t)r * H_ + h] = v;
        }
    }
}

// ---------------- kernel 6: RNN step 0 (h0 = 0) ----------------
__global__ void k_step0(const float* __restrict__ b_hh) {
    int i = blockIdx.x * blockDim.x + threadIdx.x;
    if (i >= B_ * H_) return;
    int b = i / H_, h = i - b * H_;
    g_hbuf[0][i] = tanhf(g_xproj[(size_t)b * 6 * H_ + h] + b_hh[h]);
}

// ---------------- kernel 7: gated mix ----------------
__global__ void k_final(float* __restrict__ out) {
    int i = blockIdx.x * blockDim.x + threadIdx.x;
    if (i >= B_ * H_) return;
    int b = i / H_, h = i - b * H_;
    float g = g_gate[i];
    float direct = g_xproj[(size_t)b * 6 * H_ + h];
    out[i] = g * g_hbuf[1][i] + (1.f - g) * direct;
}

// ---------------- launch ----------------
extern "C" void kernel_launch(void* const* d_in, const int* in_sizes, int n_in,
                              void* d_out, int out_size) {
    const float* query  = (const float*)d_in[0];
    const float* mem    = (const float*)d_in[1];
    const float* coords = (const float*)d_in[2];
    const float* sw     = (const float*)d_in[3];
    const float* W_ih   = (const float*)d_in[4];
    const float* b_ih   = (const float*)d_in[5];
    const float* W_hh   = (const float*)d_in[6];
    const float* b_hh   = (const float*)d_in[7];
    const float* W_g    = (const float*)d_in[8];
    const float* b_g    = (const float*)d_in[9];
    float* out = (float*)d_out;

    k_center<<<1, 128>>>(sw);
    k_prep<<<(M_ + B_) / 8, 256>>>(query, mem, coords);

    size_t smain = (size_t)(D_ * QTP + KC * MTP) * sizeof(float);
    cudaFuncSetAttribute(k_main, cudaFuncAttributeMaxDynamicSharedMemorySize, (int)smain);
    k_main<<<dim3(MS_, B_ / QT), 256, smain>>>(query, mem);

    k_topkfinal<<<4, 256>>>();

    // x_proj for all 6 timesteps (rows gathered via g_topk)
    k_gemm<<<dim3(6 * B_ / GBM, H_ / GBN), 256>>>(0, 0, 0, 0, W_ih, b_ih, query, mem);
    // gate
    k_gemm<<<dim3(B_ / GBM, H_ / GBN), 256>>>(1, 0, 0, 0, W_g, b_g, query, mem);
    // RNN
    k_step0<<<(B_ * H_) / 256, 256>>>(b_hh);
    for (int t = 1; t <= 5; t++) {
        k_gemm<<<dim3(B_ / GBM, H_ / GBN), 256>>>(2, t, (t + 1) & 1, t & 1,
                                                  W_hh, b_hh, query, mem);
    }
    k_final<<<(B_ * H_) / 256, 256>>>(out);
}

// round 4
// speedup vs baseline: 2.3717x; 2.3717x over previous
#include <cuda_runtime.h>
#include <cuda_fp16.h>
#include <stdint.h>
#include <math.h>

#define B_  1024
#define M_  65536
#define D_  384
#define H_  384
#define K_  5

// ---- main kernel tiling ----
#define CH_   8
#define MCH   (M_/CH_)
#define BQ    64
#define BN    128
#define BK    64
#define NT_   (MCH/BN)
#define QS    392
#define BSR   72
#define SCS   132

// smem byte offsets
#define SM_QHI 0
#define SM_QLO 50176
#define SM_B   100352
#define BHALF  18432
#define BSTG   36864
#define SM_SC  174080
#define SM_TOT 207872

// ---- epilogue GEMM tiling ----
#define KC  32
#define QTP 68
#define MTP 132
#define GBM 64
#define GBN 128

// ---------------- ptx macros ----------------
#define CP_ASYNC16(dst, src) \
    asm volatile("cp.async.ca.shared.global [%0], [%1], 16;" :: "r"(dst), "l"(src))
#define CP_COMMIT() asm volatile("cp.async.commit_group;" ::: "memory")
#define CP_WAIT1()  asm volatile("cp.async.wait_group 1;" ::: "memory")
#define CP_WAIT0()  asm volatile("cp.async.wait_group 0;" ::: "memory")
#define LDM4(r0, r1, r2, r3, addr) \
    asm volatile("ldmatrix.sync.aligned.m8n8.x4.shared.b16 {%0,%1,%2,%3}, [%4];" \
                 : "=r"(r0), "=r"(r1), "=r"(r2), "=r"(r3) : "r"(addr))
#define MMA16816(c0, c1, c2, c3, a0, a1, a2, a3, b0, b1) \
    asm volatile("mma.sync.aligned.m16n8k16.row.col.f32.f16.f16.f32 " \
                 "{%0,%1,%2,%3}, {%4,%5,%6,%7}, {%8,%9}, {%0,%1,%2,%3};" \
                 : "+f"(c0), "+f"(c1), "+f"(c2), "+f"(c3) \
                 : "r"(a0), "r"(a1), "r"(a2), "r"(a3), "r"(b0), "r"(b1))

// ---------------- scratch (device globals; no allocation) ----------------
__device__ float g_center[2];
__device__ float g_act[M_];
__device__ float g_rm[M_];
__device__ float g_rq[B_];
__device__ float g_candv[B_ * CH_ * K_];
__device__ int   g_candi[B_ * CH_ * K_];
__device__ int   g_topk[B_ * K_];
__device__ float g_xproj[B_ * 6 * H_];
__device__ float g_gate[B_ * H_];
__device__ float g_hbuf[2][B_ * H_];
__device__ __half g_mem_hi[M_ * D_];
__device__ __half g_mem_lo[M_ * D_];
__device__ __half g_q_hi[B_ * D_];
__device__ __half g_q_lo[B_ * D_];

// ---------------- kernel 0: fp32 -> fp16 hi/lo split ----------------
__global__ void k_split(const float* __restrict__ q, const float* __restrict__ mem) {
    const int n4m = M_ * D_ / 4;
    const int n4q = B_ * D_ / 4;
    int i = blockIdx.x * blockDim.x + threadIdx.x;
    if (i >= n4m + n4q) return;
    float4 v;
    if (i < n4m) v = ((const float4*)mem)[i];
    else         v = ((const float4*)q)[i - n4m];
    float xs[4];
    xs[0] = v.x; xs[1] = v.y; xs[2] = v.z; xs[3] = v.w;
    uint32_t hw[4], lw[4];
    #pragma unroll
    for (int k = 0; k < 4; k++) {
        __half hb = __float2half_rn(xs[k]);
        float lf = xs[k] - __half2float(hb);
        __half lb = __float2half_rn(lf);
        hw[k] = (uint32_t)__half_as_ushort(hb);
        lw[k] = (uint32_t)__half_as_ushort(lb);
    }
    uint2 hp, lp;
    hp.x = hw[0] | (hw[1] << 16); hp.y = hw[2] | (hw[3] << 16);
    lp.x = lw[0] | (lw[1] << 16); lp.y = lw[2] | (lw[3] << 16);
    if (i < n4m) {
        ((uint2*)g_mem_hi)[i] = hp;
        ((uint2*)g_mem_lo)[i] = lp;
    } else {
        ((uint2*)g_q_hi)[i - n4m] = hp;
        ((uint2*)g_q_lo)[i - n4m] = lp;
    }
}

// ---------------- kernel 1: center of spatial_weights ----------------
__global__ void k_center(const float* __restrict__ sw) {
    __shared__ float s0[128], s1[128];
    int i = threadIdx.x;
    float a = 0.f, b = 0.f;
    for (int j = i; j < H_; j += 128) { a += sw[j * 2]; b += sw[j * 2 + 1]; }
    s0[i] = a; s1[i] = b;
    __syncthreads();
    for (int off = 64; off > 0; off >>= 1) {
        if (i < off) { s0[i] += s0[i + off]; s1[i] += s1[i + off]; }
        __syncthreads();
    }
    if (i == 0) { g_center[0] = s0[0] / (float)H_; g_center[1] = s1[0] / (float)H_; }
}

// ---------------- kernel 2: per-row stats ----------------
__global__ void k_prep(const float* __restrict__ query,
                       const float* __restrict__ mem,
                       const float* __restrict__ coords) {
    int w = (blockIdx.x * blockDim.x + threadIdx.x) >> 5;
    int lane = threadIdx.x & 31;
    if (w < M_) {
        const float* row = mem + (size_t)w * D_;
        float ss = 0.f;
        #pragma unroll
        for (int j = 0; j < D_ / 32; j++) { float v = row[lane + j * 32]; ss += v * v; }
        #pragma unroll
        for (int o = 16; o; o >>= 1) ss += __shfl_xor_sync(0xffffffffu, ss, o);
        if (lane == 0) {
            g_rm[w] = 1.f / sqrtf(ss);
            float dx = coords[2 * w]     - g_center[0];
            float dy = coords[2 * w + 1] - g_center[1];
            g_act[w] = 1.f / (1.f + sqrtf(dx * dx + dy * dy));
        }
    } else if (w < M_ + B_) {
        int b = w - M_;
        const float* row = query + (size_t)b * D_;
        float ss = 0.f;
        #pragma unroll
        for (int j = 0; j < D_ / 32; j++) { float v = row[lane + j * 32]; ss += v * v; }
        #pragma unroll
        for (int o = 16; o; o >>= 1) ss += __shfl_xor_sync(0xffffffffu, ss, o);
        if (lane == 0) g_rq[b] = 1.f / sqrtf(ss);
    }
}

// ---------------- kernel 3: tensor-core GEMM + per-chunk top-5 ----------------
__global__ void __launch_bounds__(256, 1) k_main() {
    extern __shared__ char smbuf[];
    __half* qhi = (__half*)(smbuf + SM_QHI);
    __half* qlo = (__half*)(smbuf + SM_QLO);
    float* scores = (float*)(smbuf + SM_SC);
    uint32_t sbase;
    {
        uint64_t tmp = __cvta_generic_to_shared(smbuf);
        sbase = (uint32_t)tmp;
    }

    int tid = threadIdx.x;
    int lane = tid & 31;
    int wid = tid >> 5;
    int wq = (wid >> 2) * 32;
    int wm = (wid & 3) * 32;
    int qb = blockIdx.y * BQ;
    int mg0 = blockIdx.x * MCH;

    // resident Q hi/lo tiles (row q, stride QS half)
    for (int i = tid; i < BQ * 48; i += 256) {
        int r = i / 48;
        int c = i - r * 48;
        ((uint4*)(qhi + r * QS))[c] = ((const uint4*)(g_q_hi + (qb + r) * D_))[c];
        ((uint4*)(qlo + r * QS))[c] = ((const uint4*)(g_q_lo + (qb + r) * D_))[c];
    }

    float rqv = g_rq[qb + (tid >> 2)];
    float tv[K_];
    int tix[K_];
    #pragma unroll
    for (int s = 0; s < K_; s++) { tv[s] = -3.4e38f; tix[s] = 0; }

    __syncthreads();

    for (int t = 0; t < NT_; t++) {
        int mg = mg0 + t * BN;
        const __half* bh_g = g_mem_hi + (size_t)mg * D_;
        const __half* bl_g = g_mem_lo + (size_t)mg * D_;

        float acc[2][4][4];
        #pragma unroll
        for (int a = 0; a < 2; a++) {
            #pragma unroll
            for (int b = 0; b < 4; b++) {
                #pragma unroll
                for (int c = 0; c < 4; c++) acc[a][b][c] = 0.f;
            }
        }

        // prefetch stage 0 (k = 0..63)
        {
            uint32_t dst = sbase + SM_B;
            #pragma unroll
            for (int l = 0; l < 4; l++) {
                int i = tid + l * 256;
                int r = i >> 3;
                int seg = i & 7;
                uint32_t doff = (uint32_t)(r * (BSR * 2) + seg * 16);
                size_t goff = (size_t)r * D_ + seg * 8;
                CP_ASYNC16(dst + doff, (const void*)(bh_g + goff));
                CP_ASYNC16(dst + BHALF + doff, (const void*)(bl_g + goff));
            }
            CP_COMMIT();
        }

        for (int s = 0; s < 6; s++) {
            if (s < 5) {
                uint32_t dst = sbase + SM_B + (uint32_t)(((s + 1) & 1) * BSTG);
                int kc = (s + 1) * BK;
                #pragma unroll
                for (int l = 0; l < 4; l++) {
                    int i = tid + l * 256;
                    int r = i >> 3;
                    int seg = i & 7;
                    uint32_t doff = (uint32_t)(r * (BSR * 2) + seg * 16);
                    size_t goff = (size_t)r * D_ + kc + seg * 8;
                    CP_ASYNC16(dst + doff, (const void*)(bh_g + goff));
                    CP_ASYNC16(dst + BHALF + doff, (const void*)(bl_g + goff));
                }
                CP_COMMIT();
                CP_WAIT1();
            } else {
                CP_WAIT0();
            }
            __syncthreads();

            uint32_t bbuf = sbase + SM_B + (uint32_t)((s & 1) * BSTG);
            #pragma unroll
            for (int ks = 0; ks < 4; ks++) {
                int kk = s * BK + ks * 16;
                uint32_t ah[2][4], al[2][4];
                #pragma unroll
                for (int mt = 0; mt < 2; mt++) {
                    uint32_t qrow = (uint32_t)(wq + mt * 16 + (lane & 15));
                    uint32_t qcol = (uint32_t)(kk + ((lane >> 4) << 3));
                    uint32_t aoff = (qrow * QS + qcol) * 2;
                    LDM4(ah[mt][0], ah[mt][1], ah[mt][2], ah[mt][3],
                         sbase + SM_QHI + aoff);
                    LDM4(al[mt][0], al[mt][1], al[mt][2], al[mt][3],
                         sbase + SM_QLO + aoff);
                }
                uint32_t bh[4][2], bl[4][2];
                #pragma unroll
                for (int p = 0; p < 2; p++) {
                    uint32_t n = (uint32_t)(wm + p * 16 + ((lane >> 4) << 3) + (lane & 7));
                    uint32_t kcol = (uint32_t)(ks * 16 + (((lane >> 3) & 1) << 3));
                    uint32_t boff = (n * BSR + kcol) * 2;
                    uint32_t r0, r1, r2, r3;
                    LDM4(r0, r1, r2, r3, bbuf + boff);
                    bh[2 * p][0] = r0; bh[2 * p][1] = r1;
                    bh[2 * p + 1][0] = r2; bh[2 * p + 1][1] = r3;
                    LDM4(r0, r1, r2, r3, bbuf + BHALF + boff);
                    bl[2 * p][0] = r0; bl[2 * p][1] = r1;
                    bl[2 * p + 1][0] = r2; bl[2 * p + 1][1] = r3;
                }
                #pragma unroll
                for (int mt = 0; mt < 2; mt++) {
                    #pragma unroll
                    for (int nt = 0; nt < 4; nt++) {
                        MMA16816(acc[mt][nt][0], acc[mt][nt][1], acc[mt][nt][2], acc[mt][nt][3],
                                 ah[mt][0], ah[mt][1], ah[mt][2], ah[mt][3],
                                 bh[nt][0], bh[nt][1]);
                        MMA16816(acc[mt][nt][0], acc[mt][nt][1], acc[mt][nt][2], acc[mt][nt][3],
                                 al[mt][0], al[mt][1], al[mt][2], al[mt][3],
                                 bh[nt][0], bh[nt][1]);
                        MMA16816(acc[mt][nt][0], acc[mt][nt][1], acc[mt][nt][2], acc[mt][nt][3],
                                 ah[mt][0], ah[mt][1], ah[mt][2], ah[mt][3],
                                 bl[nt][0], bl[nt][1]);
                    }
                }
            }
            __syncthreads();
        }

        // stage scores to smem
        #pragma unroll
        for (int mt = 0; mt < 2; mt++) {
            #pragma unroll
            for (int nt = 0; nt < 4; nt++) {
                int q0 = wq + mt * 16 + (lane >> 2);
                int m0 = wm + nt * 8 + 2 * (lane & 3);
                scores[q0 * SCS + m0]           = acc[mt][nt][0];
                scores[q0 * SCS + m0 + 1]       = acc[mt][nt][1];
                scores[(q0 + 8) * SCS + m0]     = acc[mt][nt][2];
                scores[(q0 + 8) * SCS + m0 + 1] = acc[mt][nt][3];
            }
        }
        __syncthreads();

        // fused scale + spatial act + per-thread top-5
        {
            int tq = tid >> 2;
            int sub = tid & 3;
            #pragma unroll 4
            for (int j = 0; j < 32; j++) {
                int ml = sub * 32 + j;
                int m = mg + ml;
                float sc = fminf(rqv * g_rm[m], 1e8f);
                float v = fmaf(scores[tq * SCS + ml], sc, g_act[m]);
                if (v > tv[K_ - 1]) {
                    float cv = v;
                    int ci = m;
                    #pragma unroll
                    for (int s = 0; s < K_; s++) {
                        bool gt = cv > tv[s];
                        float ov = tv[s]; int oi = tix[s];
                        tv[s]  = gt ? cv : ov;
                        tix[s] = gt ? ci : oi;
                        cv = gt ? ov : cv;
                        ci = gt ? oi : ci;
                    }
                }
            }
        }
        __syncthreads();
    }

    // cross-thread merge (4 sub-threads per query)
    float* mv = scores;
    int*   mi = (int*)(scores + BQ * 4 * K_);
    {
        int tq = tid >> 2;
        int sub = tid & 3;
        #pragma unroll
        for (int s = 0; s < K_; s++) {
            mv[(tq * 4 + sub) * K_ + s] = tv[s];
            mi[(tq * 4 + sub) * K_ + s] = tix[s];
        }
    }
    __syncthreads();
    if (tid < BQ) {
        float bv[K_];
        int bi[K_];
        #pragma unroll
        for (int s = 0; s < K_; s++) { bv[s] = -3.4e38f; bi[s] = 0; }
        #pragma unroll
        for (int c = 0; c < 4 * K_; c++) {
            float v = mv[tid * 20 + c];
            int  ix = mi[tid * 20 + c];
            if (v > bv[K_ - 1]) {
                float cv = v;
                int ci = ix;
                #pragma unroll
                for (int s = 0; s < K_; s++) {
                    bool gt = cv > bv[s];
                    float ov = bv[s]; int oi = bi[s];
                    bv[s] = gt ? cv : ov;
                    bi[s] = gt ? ci : oi;
                    cv = gt ? ov : cv;
                    ci = gt ? oi : ci;
                }
            }
        }
        int b = qb + tid;
        #pragma unroll
        for (int s = 0; s < K_; s++) {
            g_candv[b * (CH_ * K_) + blockIdx.x * K_ + s] = bv[s];
            g_candi[b * (CH_ * K_) + blockIdx.x * K_ + s] = bi[s];
        }
    }
}

// ---------------- kernel 4: merge chunks -> final top-5 ----------------
__global__ void k_topkfinal() {
    int b = blockIdx.x * blockDim.x + threadIdx.x;
    if (b >= B_) return;
    float bv[K_];
    int bi[K_];
    #pragma unroll
    for (int s = 0; s < K_; s++) { bv[s] = -3.4e38f; bi[s] = 0; }
    for (int c = 0; c < CH_ * K_; c++) {
        float v = g_candv[b * (CH_ * K_) + c];
        int  ix = g_candi[b * (CH_ * K_) + c];
        if (v > bv[K_ - 1]) {
            float cv = v;
            int ci = ix;
            #pragma unroll
            for (int s = 0; s < K_; s++) {
                bool gt = cv > bv[s];
                float ov = bv[s]; int oi = bi[s];
                bv[s] = gt ? cv : ov;
                bi[s] = gt ? ci : oi;
                cv = gt ? ov : cv;
                ci = gt ? oi : ci;
            }
        }
    }
    #pragma unroll
    for (int s = 0; s < K_; s++) g_topk[b * K_ + s] = bi[s];
}

// ---------------- kernel 5: unified tiled GEMM (xproj / gate / rnn) ----------------
__global__ void __launch_bounds__(256)
k_gemm(int mode, int t, int inbuf, int outbuf,
       const float* __restrict__ W, const float* __restrict__ bias,
       const float* __restrict__ query, const float* __restrict__ mem) {
    __shared__ __align__(16) float a_s[KC * QTP];
    __shared__ __align__(16) float w_s[KC * MTP];
    int tid = threadIdx.x;
    int tx = tid & 15, ty = tid >> 4;
    int rb = blockIdx.x * GBM;
    int hb = blockIdx.y * GBN;

    float acc[4][8];
    #pragma unroll
    for (int i = 0; i < 4; i++) {
        #pragma unroll
        for (int j = 0; j < 8; j++) acc[i][j] = 0.f;
    }

    const float* Abase = (mode == 1) ? query : ((mode == 2) ? g_hbuf[inbuf] : (const float*)0);

    for (int kc = 0; kc < D_; kc += KC) {
        __syncthreads();
        #pragma unroll
        for (int l = 0; l < 2; l++) {
            int idx = tid + l * 256;
            int row = idx >> 3, k4 = idx & 7;
            int r = rb + row;
            const float* src;
            if (mode == 0) {
                int bq = r / 6;
                int tt = r - bq * 6;
                if (tt == 0) src = query + (size_t)bq * D_;
                else src = mem + (size_t)g_topk[bq * K_ + tt - 1] * D_;
            } else {
                src = Abase + (size_t)r * D_;
            }
            float4 v = *(const float4*)(src + kc + k4 * 4);
            int kl = k4 * 4;
            a_s[(kl + 0) * QTP + row] = v.x;
            a_s[(kl + 1) * QTP + row] = v.y;
            a_s[(kl + 2) * QTP + row] = v.z;
            a_s[(kl + 3) * QTP + row] = v.w;
        }
        #pragma unroll
        for (int l = 0; l < 4; l++) {
            int idx = tid + l * 256;
            int h = idx >> 3, k4 = idx & 7;
            float4 v = *(const float4*)(W + (size_t)(hb + h) * D_ + kc + k4 * 4);
            int kl = k4 * 4;
            w_s[(kl + 0) * MTP + h] = v.x;
            w_s[(kl + 1) * MTP + h] = v.y;
            w_s[(kl + 2) * MTP + h] = v.z;
            w_s[(kl + 3) * MTP + h] = v.w;
        }
        __syncthreads();

        #pragma unroll 8
        for (int k = 0; k < KC; k++) {
            float4 av  = *(const float4*)(a_s + k * QTP + ty * 4);
            float4 b0v = *(const float4*)(w_s + k * MTP + tx * 8);
            float4 b1v = *(const float4*)(w_s + k * MTP + tx * 8 + 4);
            float a[4];
            a[0] = av.x; a[1] = av.y; a[2] = av.z; a[3] = av.w;
            float bb[8];
            bb[0] = b0v.x; bb[1] = b0v.y; bb[2] = b0v.z; bb[3] = b0v.w;
            bb[4] = b1v.x; bb[5] = b1v.y; bb[6] = b1v.z; bb[7] = b1v.w;
            #pragma unroll
            for (int i = 0; i < 4; i++) {
                #pragma unroll
                for (int j = 0; j < 8; j++) acc[i][j] = fmaf(a[i], bb[j], acc[i][j]);
            }
        }
    }

    float* out = (mode == 0) ? g_xproj : ((mode == 1) ? g_gate : g_hbuf[outbuf]);
    #pragma unroll
    for (int i = 0; i < 4; i++) {
        int r = rb + ty * 4 + i;
        #pragma unroll
        for (int j = 0; j < 8; j++) {
            int h = hb + tx * 8 + j;
            float v = acc[i][j] + bias[h];
            if (mode == 2) {
                v += g_xproj[(r * 6 + t) * H_ + h];
                v = tanhf(v);
            } else if (mode == 1) {
                v = 1.f / (1.f + expf(-v));
            }
            out[r * H_ + h] = v;
        }
    }
}

// ---------------- kernel 6: RNN step 0 ----------------
__global__ void k_step0(const float* __restrict__ b_hh) {
    int i = blockIdx.x * blockDim.x + threadIdx.x;
    if (i >= B_ * H_) return;
    int b = i / H_, h = i - b * H_;
    g_hbuf[0][i] = tanhf(g_xproj[b * 6 * H_ + h] + b_hh[h]);
}

// ---------------- kernel 7: gated mix ----------------
__global__ void k_final(float* __restrict__ out) {
    int i = blockIdx.x * blockDim.x + threadIdx.x;
    if (i >= B_ * H_) return;
    int b = i / H_, h = i - b * H_;
    float g = g_gate[i];
    float direct = g_xproj[b * 6 * H_ + h];
    out[i] = g * g_hbuf[1][i] + (1.f - g) * direct;
}

// ---------------- launch ----------------
extern "C" void kernel_launch(void* const* d_in, const int* in_sizes, int n_in,
                              void* d_out, int out_size) {
    const float* query  = (const float*)d_in[0];
    const float* mem    = (const float*)d_in[1];
    const float* coords = (const float*)d_in[2];
    const float* sw     = (const float*)d_in[3];
    const float* W_ih   = (const float*)d_in[4];
    const float* b_ih   = (const float*)d_in[5];
    const float* W_hh   = (const float*)d_in[6];
    const float* b_hh   = (const float*)d_in[7];
    const float* W_g    = (const float*)d_in[8];
    const float* b_g    = (const float*)d_in[9];
    float* out = (float*)d_out;

    int nsplit = (M_ * D_ + B_ * D_) / 4;
    k_split<<<(nsplit + 255) / 256, 256>>>(query, mem);
    k_center<<<1, 128>>>(sw);
    k_prep<<<(M_ + B_) / 8, 256>>>(query, mem, coords);

    cudaFuncSetAttribute(k_main, cudaFuncAttributeMaxDynamicSharedMemorySize, SM_TOT);
    k_main<<<dim3(CH_, B_ / BQ), 256, SM_TOT>>>();

    k_topkfinal<<<4, 256>>>();

    k_gemm<<<dim3(6 * B_ / GBM, H_ / GBN), 256>>>(0, 0, 0, 0, W_ih, b_ih, query, mem);
    k_gemm<<<dim3(B_ / GBM, H_ / GBN), 256>>>(1, 0, 0, 0, W_g, b_g, query, mem);
    k_step0<<<(B_ * H_) / 256, 256>>>(b_hh);
    for (int t = 1; t <= 5; t++) {
        k_gemm<<<dim3(B_ / GBM, H_ / GBN), 256>>>(2, t, (t + 1) & 1, t & 1,
                                                  W_hh, b_hh, query, mem);
    }
    k_final<<<(B_ * H_) / 256, 256>>>(out);
}

// round 5
// speedup vs baseline: 2.5139x; 1.0600x over previous
#include <cuda_runtime.h>
#include <cuda_fp16.h>
#include <stdint.h>
#include <math.h>

#define B_  1024
#define M_  65536
#define D_  384
#define H_  384
#define K_  5

// ---- main kernel tiling ----
#define CH_   8
#define MCH   (M_/CH_)      // 8192
#define BQ    64
#define BN    256
#define BK    64
#define NT_   (MCH/BN)      // 32

// smem byte offsets (k_main)
#define SM_QLO 49152                 // Q hi at 0, 64*768B each
#define SM_B   98304
#define BHALF  32768                 // 256 rows * 128B
#define BSTG   65536                 // hi+lo per stage
#define SM_TOT 229376                // SM_B + 2*BSTG

// ---- epilogue GEMM tiling ----
#define KC  32
#define QTP 68
#define MTP 132
#define GBM 64
#define GBN 128

#define RNS 36                       // k_rnn W smem row stride (floats)

// ---------------- ptx macros ----------------
#define CP_ASYNC16(dst, src) \
    asm volatile("cp.async.ca.shared.global [%0], [%1], 16;" :: "r"(dst), "l"(src))
#define CP_COMMIT() asm volatile("cp.async.commit_group;" ::: "memory")
#define CP_WAIT1()  asm volatile("cp.async.wait_group 1;" ::: "memory")
#define CP_WAIT0()  asm volatile("cp.async.wait_group 0;" ::: "memory")
#define LDM4(r0, r1, r2, r3, addr) \
    asm volatile("ldmatrix.sync.aligned.m8n8.x4.shared.b16 {%0,%1,%2,%3}, [%4];" \
                 : "=r"(r0), "=r"(r1), "=r"(r2), "=r"(r3) : "r"(addr))
#define MMA16816(c0, c1, c2, c3, a0, a1, a2, a3, b0, b1) \
    asm volatile("mma.sync.aligned.m16n8k16.row.col.f32.f16.f16.f32 " \
                 "{%0,%1,%2,%3}, {%4,%5,%6,%7}, {%8,%9}, {%0,%1,%2,%3};" \
                 : "+f"(c0), "+f"(c1), "+f"(c2), "+f"(c3) \
                 : "r"(a0), "r"(a1), "r"(a2), "r"(a3), "r"(b0), "r"(b1))

// ---------------- scratch (device globals; no allocation) ----------------
__device__ float  g_center[2];
__device__ float2 g_ra[M_];          // (1/||m||, act)
__device__ float  g_rq[B_];
__device__ float  g_candv[B_ * CH_ * K_];
__device__ int    g_candi[B_ * CH_ * K_];
__device__ int    g_topk[B_ * K_];
__device__ float  g_xproj[B_ * 6 * H_];
__device__ float  g_gate[B_ * H_];
__device__ __half g_mem_hi[M_ * D_];
__device__ __half g_mem_lo[M_ * D_];
__device__ __half g_q_hi[B_ * D_];
__device__ __half g_q_lo[B_ * D_];

// ---------------- kernel 0: fp32 -> fp16 hi/lo split ----------------
__global__ void k_split(const float* __restrict__ q, const float* __restrict__ mem) {
    const int n4m = M_ * D_ / 4;
    const int n4q = B_ * D_ / 4;
    int i = blockIdx.x * blockDim.x + threadIdx.x;
    if (i >= n4m + n4q) return;
    float4 v;
    if (i < n4m) v = ((const float4*)mem)[i];
    else         v = ((const float4*)q)[i - n4m];
    float xs[4];
    xs[0] = v.x; xs[1] = v.y; xs[2] = v.z; xs[3] = v.w;
    uint32_t hw[4], lw[4];
    #pragma unroll
    for (int k = 0; k < 4; k++) {
        __half hb = __float2half_rn(xs[k]);
        float lf = xs[k] - __half2float(hb);
        __half lb = __float2half_rn(lf);
        hw[k] = (uint32_t)__half_as_ushort(hb);
        lw[k] = (uint32_t)__half_as_ushort(lb);
    }
    uint2 hp, lp;
    hp.x = hw[0] | (hw[1] << 16); hp.y = hw[2] | (hw[3] << 16);
    lp.x = lw[0] | (lw[1] << 16); lp.y = lw[2] | (lw[3] << 16);
    if (i < n4m) {
        ((uint2*)g_mem_hi)[i] = hp;
        ((uint2*)g_mem_lo)[i] = lp;
    } else {
        ((uint2*)g_q_hi)[i - n4m] = hp;
        ((uint2*)g_q_lo)[i - n4m] = lp;
    }
}

// ---------------- kernel 1: center of spatial_weights ----------------
__global__ void k_center(const float* __restrict__ sw) {
    __shared__ float s0[128], s1[128];
    int i = threadIdx.x;
    float a = 0.f, b = 0.f;
    for (int j = i; j < H_; j += 128) { a += sw[j * 2]; b += sw[j * 2 + 1]; }
    s0[i] = a; s1[i] = b;
    __syncthreads();
    for (int off = 64; off > 0; off >>= 1) {
        if (i < off) { s0[i] += s0[i + off]; s1[i] += s1[i + off]; }
        __syncthreads();
    }
    if (i == 0) { g_center[0] = s0[0] / (float)H_; g_center[1] = s1[0] / (float)H_; }
}

// ---------------- kernel 2: per-row stats ----------------
__global__ void k_prep(const float* __restrict__ query,
                       const float* __restrict__ mem,
                       const float* __restrict__ coords) {
    int w = (blockIdx.x * blockDim.x + threadIdx.x) >> 5;
    int lane = threadIdx.x & 31;
    if (w < M_) {
        const float* row = mem + (size_t)w * D_;
        float ss = 0.f;
        #pragma unroll
        for (int j = 0; j < D_ / 32; j++) { float v = row[lane + j * 32]; ss += v * v; }
        #pragma unroll
        for (int o = 16; o; o >>= 1) ss += __shfl_xor_sync(0xffffffffu, ss, o);
        if (lane == 0) {
            float dx = coords[2 * w]     - g_center[0];
            float dy = coords[2 * w + 1] - g_center[1];
            float2 ra;
            ra.x = 1.f / sqrtf(ss);
            ra.y = 1.f / (1.f + sqrtf(dx * dx + dy * dy));
            g_ra[w] = ra;
        }
    } else if (w < M_ + B_) {
        int b = w - M_;
        const float* row = query + (size_t)b * D_;
        float ss = 0.f;
        #pragma unroll
        for (int j = 0; j < D_ / 32; j++) { float v = row[lane + j * 32]; ss += v * v; }
        #pragma unroll
        for (int o = 16; o; o >>= 1) ss += __shfl_xor_sync(0xffffffffu, ss, o);
        if (lane == 0) g_rq[b] = 1.f / sqrtf(ss);
    }
}

// ---------------- kernel 3: tensor-core GEMM + register top-5 ----------------
__global__ void __launch_bounds__(256, 1) k_main() {
    extern __shared__ char smbuf[];
    uint32_t sbase;
    {
        uint64_t tmp = __cvta_generic_to_shared(smbuf);
        sbase = (uint32_t)tmp;
    }

    int tid = threadIdx.x;
    int lane = tid & 31;
    int wid = tid >> 5;
    int wq = (wid >> 2) * 32;       // 0 or 32
    int wm = (wid & 3) * 64;        // 0,64,128,192
    int qb = blockIdx.y * BQ;
    int mg0 = blockIdx.x * MCH;

    // resident Q hi/lo (swizzled: 16B chunk c of row r goes to chunk (c&~7)|((c^r)&7))
    for (int i = tid; i < BQ * 48; i += 256) {
        int r = i / 48;
        int c = i - r * 48;
        int cs = (c & ~7) | ((c ^ r) & 7);
        *(uint4*)(smbuf + r * 768 + cs * 16) = ((const uint4*)(g_q_hi + (qb + r) * D_))[c];
        *(uint4*)(smbuf + SM_QLO + r * 768 + cs * 16) = ((const uint4*)(g_q_lo + (qb + r) * D_))[c];
    }

    float rq[4];
    #pragma unroll
    for (int l = 0; l < 4; l++)
        rq[l] = g_rq[qb + wq + (l >> 1) * 16 + (l & 1) * 8 + (lane >> 2)];

    float tv[4][K_];
    int   tix[4][K_];
    #pragma unroll
    for (int l = 0; l < 4; l++) {
        #pragma unroll
        for (int s = 0; s < K_; s++) { tv[l][s] = -3.4e38f; tix[l][s] = 0; }
    }

    __syncthreads();

    // initial prefetch: tile 0, stage 0 -> buf 0
    {
        const __half* bh_g = g_mem_hi + (size_t)mg0 * D_;
        const __half* bl_g = g_mem_lo + (size_t)mg0 * D_;
        uint32_t dst = sbase + SM_B;
        #pragma unroll
        for (int l = 0; l < 8; l++) {
            int i = tid + l * 256;
            int r = i >> 3;
            int seg = i & 7;
            uint32_t doff = (uint32_t)(r * 128 + (((seg ^ r) & 7) << 4));
            size_t goff = (size_t)r * D_ + seg * 8;
            CP_ASYNC16(dst + doff, (const void*)(bh_g + goff));
            CP_ASYNC16(dst + BHALF + doff, (const void*)(bl_g + goff));
        }
        CP_COMMIT();
    }

    for (int t = 0; t < NT_; t++) {
        int mg = mg0 + t * BN;

        float acc[2][8][4];
        #pragma unroll
        for (int a = 0; a < 2; a++) {
            #pragma unroll
            for (int b = 0; b < 8; b++) {
                #pragma unroll
                for (int c = 0; c < 4; c++) acc[a][b][c] = 0.f;
            }
        }

        for (int s = 0; s < 6; s++) {
            bool issue = (s < 5) || (t + 1 < NT_);
            if (issue) {
                int kc, mnext;
                uint32_t dst;
                if (s < 5) { kc = (s + 1) * BK; mnext = mg; dst = sbase + SM_B + (uint32_t)(((s + 1) & 1) * BSTG); }
                else       { kc = 0; mnext = mg + BN; dst = sbase + SM_B; }
                const __half* bh_g = g_mem_hi + (size_t)mnext * D_;
                const __half* bl_g = g_mem_lo + (size_t)mnext * D_;
                #pragma unroll
                for (int l = 0; l < 8; l++) {
                    int i = tid + l * 256;
                    int r = i >> 3;
                    int seg = i & 7;
                    uint32_t doff = (uint32_t)(r * 128 + (((seg ^ r) & 7) << 4));
                    size_t goff = (size_t)r * D_ + kc + seg * 8;
                    CP_ASYNC16(dst + doff, (const void*)(bh_g + goff));
                    CP_ASYNC16(dst + BHALF + doff, (const void*)(bl_g + goff));
                }
                CP_COMMIT();
                CP_WAIT1();
            } else {
                CP_WAIT0();
            }
            __syncthreads();

            uint32_t bbuf = sbase + SM_B + (uint32_t)((s & 1) * BSTG);
            #pragma unroll
            for (int ks = 0; ks < 4; ks++) {
                int c16 = s * 8 + ks * 2 + (lane >> 4);
                uint32_t ah[2][4], al[2][4];
                #pragma unroll
                for (int mt = 0; mt < 2; mt++) {
                    int qrow = wq + mt * 16 + (lane & 15);
                    int cs = (c16 & ~7) | ((c16 ^ qrow) & 7);
                    uint32_t aoff = (uint32_t)(qrow * 768 + cs * 16);
                    LDM4(ah[mt][0], ah[mt][1], ah[mt][2], ah[mt][3], sbase + aoff);
                    LDM4(al[mt][0], al[mt][1], al[mt][2], al[mt][3], sbase + SM_QLO + aoff);
                }
                uint32_t bhf[8][2], blf[8][2];
                #pragma unroll
                for (int p = 0; p < 4; p++) {
                    int n = wm + p * 16 + ((lane >> 4) << 3) + (lane & 7);
                    int cb = ks * 2 + ((lane >> 3) & 1);
                    uint32_t boff = (uint32_t)(n * 128 + (((cb ^ n) & 7) << 4));
                    uint32_t r0, r1, r2, r3;
                    LDM4(r0, r1, r2, r3, bbuf + boff);
                    bhf[2 * p][0] = r0; bhf[2 * p][1] = r1;
                    bhf[2 * p + 1][0] = r2; bhf[2 * p + 1][1] = r3;
                    LDM4(r0, r1, r2, r3, bbuf + BHALF + boff);
                    blf[2 * p][0] = r0; blf[2 * p][1] = r1;
                    blf[2 * p + 1][0] = r2; blf[2 * p + 1][1] = r3;
                }
                #pragma unroll
                for (int mt = 0; mt < 2; mt++) {
                    #pragma unroll
                    for (int nt = 0; nt < 8; nt++) {
                        MMA16816(acc[mt][nt][0], acc[mt][nt][1], acc[mt][nt][2], acc[mt][nt][3],
                                 ah[mt][0], ah[mt][1], ah[mt][2], ah[mt][3],
                                 bhf[nt][0], bhf[nt][1]);
                        MMA16816(acc[mt][nt][0], acc[mt][nt][1], acc[mt][nt][2], acc[mt][nt][3],
                                 al[mt][0], al[mt][1], al[mt][2], al[mt][3],
                                 bhf[nt][0], bhf[nt][1]);
                        MMA16816(acc[mt][nt][0], acc[mt][nt][1], acc[mt][nt][2], acc[mt][nt][3],
                                 ah[mt][0], ah[mt][1], ah[mt][2], ah[mt][3],
                                 blf[nt][0], blf[nt][1]);
                    }
                }
            }
            __syncthreads();
        }

        // register epilogue: scale + spatial act + top-5 insert (no smem)
        #pragma unroll
        for (int mt = 0; mt < 2; mt++) {
            #pragma unroll
            for (int nt = 0; nt < 8; nt++) {
                int m0 = mg + wm + nt * 8 + 2 * (lane & 3);
                float4 rr4 = *(const float4*)(&g_ra[m0]);   // rm0, act0, rm1, act1
                #pragma unroll
                for (int c = 0; c < 4; c++) {
                    int lst = mt * 2 + (c >> 1);
                    float rm  = (c & 1) ? rr4.z : rr4.x;
                    float act = (c & 1) ? rr4.w : rr4.y;
                    float v = fmaf(acc[mt][nt][c], fminf(rq[lst] * rm, 1e8f), act);
                    if (v > tv[lst][K_ - 1]) {
                        float cv = v;
                        int ci = m0 + (c & 1);
                        #pragma unroll
                        for (int s = 0; s < K_; s++) {
                            bool gt = cv > tv[lst][s];
                            float ov = tv[lst][s]; int oi = tix[lst][s];
                            tv[lst][s]  = gt ? cv : ov;
                            tix[lst][s] = gt ? ci : oi;
                            cv = gt ? ov : cv;
                            ci = gt ? oi : ci;
                        }
                    }
                }
            }
        }
    }

    // final merge via smem (aliases Q region)
    __syncthreads();
    float* mv = (float*)smbuf;
    int*   mi = (int*)(smbuf + 20480);
    int slot = (wid & 3) * 4 + (lane & 3);
    #pragma unroll
    for (int l = 0; l < 4; l++) {
        int q = wq + (l >> 1) * 16 + (l & 1) * 8 + (lane >> 2);
        #pragma unroll
        for (int s = 0; s < K_; s++) {
            mv[(q * 16 + slot) * K_ + s] = tv[l][s];
            mi[(q * 16 + slot) * K_ + s] = tix[l][s];
        }
    }
    __syncthreads();
    if (tid < BQ) {
        float bv[K_];
        int bi[K_];
        #pragma unroll
        for (int s = 0; s < K_; s++) { bv[s] = -3.4e38f; bi[s] = 0; }
        #pragma unroll 4
        for (int c = 0; c < 16 * K_; c++) {
            float v = mv[tid * 80 + c];
            int  ix = mi[tid * 80 + c];
            if (v > bv[K_ - 1]) {
                float cv = v;
                int ci = ix;
                #pragma unroll
                for (int s = 0; s < K_; s++) {
                    bool gt = cv > bv[s];
                    float ov = bv[s]; int oi = bi[s];
                    bv[s] = gt ? cv : ov;
                    bi[s] = gt ? ci : oi;
                    cv = gt ? ov : cv;
                    ci = gt ? oi : ci;
                }
            }
        }
        int b = qb + tid;
        #pragma unroll
        for (int s = 0; s < K_; s++) {
            g_candv[b * (CH_ * K_) + blockIdx.x * K_ + s] = bv[s];
            g_candi[b * (CH_ * K_) + blockIdx.x * K_ + s] = bi[s];
        }
    }
}

// ---------------- kernel 4: merge chunks -> final top-5 ----------------
__global__ void k_topkfinal() {
    int b = blockIdx.x * blockDim.x + threadIdx.x;
    if (b >= B_) return;
    float bv[K_];
    int bi[K_];
    #pragma unroll
    for (int s = 0; s < K_; s++) { bv[s] = -3.4e38f; bi[s] = 0; }
    for (int c = 0; c < CH_ * K_; c++) {
        float v = g_candv[b * (CH_ * K_) + c];
        int  ix = g_candi[b * (CH_ * K_) + c];
        if (v > bv[K_ - 1]) {
            float cv = v;
            int ci = ix;
            #pragma unroll
            for (int s = 0; s < K_; s++) {
                bool gt = cv > bv[s];
                float ov = bv[s]; int oi = bi[s];
                bv[s] = gt ? cv : ov;
                bi[s] = gt ? ci : oi;
                cv = gt ? ov : cv;
                ci = gt ? oi : ci;
            }
        }
    }
    #pragma unroll
    for (int s = 0; s < K_; s++) g_topk[b * K_ + s] = bi[s];
}

// ---------------- kernel 5: tiled GEMM (mode 0: xproj, mode 1: gate) ----------------
__global__ void __launch_bounds__(256)
k_gemm(int mode,
       const float* __restrict__ W, const float* __restrict__ bias,
       const float* __restrict__ query, const float* __restrict__ mem) {
    __shared__ __align__(16) float a_s[KC * QTP];
    __shared__ __align__(16) float w_s[KC * MTP];
    int tid = threadIdx.x;
    int tx = tid & 15, ty = tid >> 4;
    int rb = blockIdx.x * GBM;
    int hb = blockIdx.y * GBN;

    float acc[4][8];
    #pragma unroll
    for (int i = 0; i < 4; i++) {
        #pragma unroll
        for (int j = 0; j < 8; j++) acc[i][j] = 0.f;
    }

    for (int kc = 0; kc < D_; kc += KC) {
        __syncthreads();
        #pragma unroll
        for (int l = 0; l < 2; l++) {
            int idx = tid + l * 256;
            int row = idx >> 3, k4 = idx & 7;
            int r = rb + row;
            const float* src;
            if (mode == 0) {
                int bq = r / 6;
                int tt = r - bq * 6;
                if (tt == 0) src = query + (size_t)bq * D_;
                else src = mem + (size_t)g_topk[bq * K_ + tt - 1] * D_;
            } else {
                src = query + (size_t)r * D_;
            }
            float4 v = *(const float4*)(src + kc + k4 * 4);
            int kl = k4 * 4;
            a_s[(kl + 0) * QTP + row] = v.x;
            a_s[(kl + 1) * QTP + row] = v.y;
            a_s[(kl + 2) * QTP + row] = v.z;
            a_s[(kl + 3) * QTP + row] = v.w;
        }
        #pragma unroll
        for (int l = 0; l < 4; l++) {
            int idx = tid + l * 256;
            int h = idx >> 3, k4 = idx & 7;
            float4 v = *(const float4*)(W + (size_t)(hb + h) * D_ + kc + k4 * 4);
            int kl = k4 * 4;
            w_s[(kl + 0) * MTP + h] = v.x;
            w_s[(kl + 1) * MTP + h] = v.y;
            w_s[(kl + 2) * MTP + h] = v.z;
            w_s[(kl + 3) * MTP + h] = v.w;
        }
        __syncthreads();

        #pragma unroll 8
        for (int k = 0; k < KC; k++) {
            float4 av  = *(const float4*)(a_s + k * QTP + ty * 4);
            float4 b0v = *(const float4*)(w_s + k * MTP + tx * 8);
            float4 b1v = *(const float4*)(w_s + k * MTP + tx * 8 + 4);
            float a[4];
            a[0] = av.x; a[1] = av.y; a[2] = av.z; a[3] = av.w;
            float bb[8];
            bb[0] = b0v.x; bb[1] = b0v.y; bb[2] = b0v.z; bb[3] = b0v.w;
            bb[4] = b1v.x; bb[5] = b1v.y; bb[6] = b1v.z; bb[7] = b1v.w;
            #pragma unroll
            for (int i = 0; i < 4; i++) {
                #pragma unroll
                for (int j = 0; j < 8; j++) acc[i][j] = fmaf(a[i], bb[j], acc[i][j]);
            }
        }
    }

    float* out = (mode == 0) ? g_xproj : g_gate;
    #pragma unroll
    for (int i = 0; i < 4; i++) {
        int r = rb + ty * 4 + i;
        #pragma unroll
        for (int j = 0; j < 8; j++) {
            int h = hb + tx * 8 + j;
            float v = acc[i][j] + bias[h];
            if (mode == 1) v = 1.f / (1.f + expf(-v));
            out[r * H_ + h] = v;
        }
    }
}

// ---------------- kernel 6: fused RNN (step0 + 5 steps + gated mix) ----------------
__global__ void __launch_bounds__(256) k_rnn(const float* __restrict__ Whh,
                                             const float* __restrict__ bhh,
                                             float* __restrict__ out) {
    extern __shared__ float rs[];
    float* h_s = rs;                  // 8 rows * 384
    float* w_s = rs + 8 * H_;         // 384 * RNS (w_s[h][kk])
    int tid = threadIdx.x;
    int r0 = blockIdx.x * 8;

    int rr[12], hh[12];
    #pragma unroll
    for (int o = 0; o < 12; o++) {
        int idx = o * 256 + tid;
        rr[o] = idx / H_;
        hh[o] = idx - rr[o] * H_;
    }

    // step 0: h = tanh(x0 + b_hh)
    #pragma unroll
    for (int o = 0; o < 12; o++)
        h_s[rr[o] * H_ + hh[o]] = tanhf(g_xproj[(r0 + rr[o]) * (6 * H_) + hh[o]] + bhh[hh[o]]);
    __syncthreads();

    for (int t = 1; t <= 5; t++) {
        float hn[12];
        #pragma unroll
        for (int o = 0; o < 12; o++)
            hn[o] = g_xproj[(r0 + rr[o]) * (6 * H_) + t * H_ + hh[o]] + bhh[hh[o]];

        for (int k0 = 0; k0 < H_; k0 += 32) {
            __syncthreads();
            for (int i = tid; i < 32 * H_; i += 256) {
                int kk = i & 31;
                int h = i >> 5;
                w_s[h * RNS + kk] = Whh[h * H_ + k0 + kk];
            }
            __syncthreads();
            #pragma unroll
            for (int o = 0; o < 12; o++) {
                const float4* wp = (const float4*)(w_s + hh[o] * RNS);
                const float4* hp = (const float4*)(h_s + rr[o] * H_ + k0);
                float a = 0.f;
                #pragma unroll
                for (int k4 = 0; k4 < 8; k4++) {
                    float4 w4 = wp[k4];
                    float4 h4 = hp[k4];
                    a = fmaf(w4.x, h4.x, a);
                    a = fmaf(w4.y, h4.y, a);
                    a = fmaf(w4.z, h4.z, a);
                    a = fmaf(w4.w, h4.w, a);
                }
                hn[o] += a;
            }
        }
        __syncthreads();
        if (t < 5) {
            #pragma unroll
            for (int o = 0; o < 12; o++) h_s[rr[o] * H_ + hh[o]] = tanhf(hn[o]);
            __syncthreads();
        } else {
            #pragma unroll
            for (int o = 0; o < 12; o++) {
                int gi = (r0 + rr[o]) * H_ + hh[o];
                float g = g_gate[gi];
                float direct = g_xproj[(r0 + rr[o]) * (6 * H_) + hh[o]];
                out[gi] = g * tanhf(hn[o]) + (1.f - g) * direct;
            }
        }
    }
}

// ---------------- launch ----------------
extern "C" void kernel_launch(void* const* d_in, const int* in_sizes, int n_in,
                              void* d_out, int out_size) {
    const float* query  = (const float*)d_in[0];
    const float* mem    = (const float*)d_in[1];
    const float* coords = (const float*)d_in[2];
    const float* sw     = (const float*)d_in[3];
    const float* W_ih   = (const float*)d_in[4];
    const float* b_ih   = (const float*)d_in[5];
    const float* W_hh   = (const float*)d_in[6];
    const float* b_hh   = (const float*)d_in[7];
    const float* W_g    = (const float*)d_in[8];
    const float* b_g    = (const float*)d_in[9];
    float* out = (float*)d_out;

    int nsplit = (M_ * D_ + B_ * D_) / 4;
    k_split<<<(nsplit + 255) / 256, 256>>>(query, mem);
    k_center<<<1, 128>>>(sw);
    k_prep<<<(M_ + B_) / 8, 256>>>(query, mem, coords);

    cudaFuncSetAttribute(k_main, cudaFuncAttributeMaxDynamicSharedMemorySize, SM_TOT);
    k_main<<<dim3(CH_, B_ / BQ), 256, SM_TOT>>>();

    k_topkfinal<<<4, 256>>>();

    k_gemm<<<dim3(6 * B_ / GBM, H_ / GBN), 256>>>(0, W_ih, b_ih, query, mem);
    k_gemm<<<dim3(B_ / GBM, H_ / GBN), 256>>>(1, W_g, b_g, query, mem);

    int rnn_smem = (8 * H_ + H_ * RNS) * 4;
    cudaFuncSetAttribute(k_rnn, cudaFuncAttributeMaxDynamicSharedMemorySize, rnn_smem);
    k_rnn<<<B_ / 8, 256, rnn_smem>>>(W_hh, b_hh, out);
}

// round 6
// speedup vs baseline: 2.6689x; 1.0617x over previous
#include <cuda_runtime.h>
#include <cuda_fp16.h>
#include <stdint.h>
#include <math.h>

#define B_  1024
#define M_  65536
#define D_  384
#define H_  384
#define K_  5

// ---- main kernel tiling ----
#define CH_   8
#define MCH   (M_/CH_)      // 8192
#define BQ    64
#define BN    256
#define BK    64
#define NT_   (MCH/BN)      // 32

// smem byte offsets (k_main)
#define SM_QLO 49152                 // Q hi at 0, 64*768B each
#define SM_B   98304
#define BHALF  32768                 // 256 rows * 128B
#define BSTG   65536                 // hi+lo per stage
#define SM_TOT 229376                // SM_B + 2*BSTG

// ---- epilogue GEMM tiling ----
#define KC  32
#define QTP 68
#define MTP 132
#define GBM 64
#define GBN 128

#define RNS 36                       // k_rnn W smem row stride (floats)

// ---------------- ptx macros ----------------
#define CP_ASYNC16(dst, src) \
    asm volatile("cp.async.ca.shared.global [%0], [%1], 16;" :: "r"(dst), "l"(src))
#define CP_COMMIT() asm volatile("cp.async.commit_group;" ::: "memory")
#define CP_WAIT1()  asm volatile("cp.async.wait_group 1;" ::: "memory")
#define CP_WAIT0()  asm volatile("cp.async.wait_group 0;" ::: "memory")
#define LDM4(r0, r1, r2, r3, addr) \
    asm volatile("ldmatrix.sync.aligned.m8n8.x4.shared.b16 {%0,%1,%2,%3}, [%4];" \
                 : "=r"(r0), "=r"(r1), "=r"(r2), "=r"(r3) : "r"(addr))
#define MMA16816(c0, c1, c2, c3, a0, a1, a2, a3, b0, b1) \
    asm volatile("mma.sync.aligned.m16n8k16.row.col.f32.f16.f16.f32 " \
                 "{%0,%1,%2,%3}, {%4,%5,%6,%7}, {%8,%9}, {%0,%1,%2,%3};" \
                 : "+f"(c0), "+f"(c1), "+f"(c2), "+f"(c3) \
                 : "r"(a0), "r"(a1), "r"(a2), "r"(a3), "r"(b0), "r"(b1))

// ---------------- scratch (device globals; no allocation) ----------------
__device__ float  g_center[2];
__device__ float2 g_ra[M_];          // (1/||m||, act)
__device__ float  g_rq[B_];
__device__ float  g_candv[B_ * CH_ * K_];
__device__ int    g_candi[B_ * CH_ * K_];
__device__ int    g_topk[B_ * K_];
__device__ float  g_xproj[B_ * 6 * H_];
__device__ float  g_gate[B_ * H_];
__device__ __half g_mem_hi[M_ * D_];
__device__ __half g_mem_lo[M_ * D_];
__device__ __half g_q_hi[B_ * D_];
__device__ __half g_q_lo[B_ * D_];

// ---------------- kernel 0: fp32 -> fp16 hi/lo split ----------------
__global__ void k_split(const float* __restrict__ q, const float* __restrict__ mem) {
    const int n4m = M_ * D_ / 4;
    const int n4q = B_ * D_ / 4;
    int i = blockIdx.x * blockDim.x + threadIdx.x;
    if (i >= n4m + n4q) return;
    float4 v;
    if (i < n4m) v = ((const float4*)mem)[i];
    else         v = ((const float4*)q)[i - n4m];
    float xs[4];
    xs[0] = v.x; xs[1] = v.y; xs[2] = v.z; xs[3] = v.w;
    uint32_t hw[4], lw[4];
    #pragma unroll
    for (int k = 0; k < 4; k++) {
        __half hb = __float2half_rn(xs[k]);
        float lf = xs[k] - __half2float(hb);
        __half lb = __float2half_rn(lf);
        hw[k] = (uint32_t)__half_as_ushort(hb);
        lw[k] = (uint32_t)__half_as_ushort(lb);
    }
    uint2 hp, lp;
    hp.x = hw[0] | (hw[1] << 16); hp.y = hw[2] | (hw[3] << 16);
    lp.x = lw[0] | (lw[1] << 16); lp.y = lw[2] | (lw[3] << 16);
    if (i < n4m) {
        ((uint2*)g_mem_hi)[i] = hp;
        ((uint2*)g_mem_lo)[i] = lp;
    } else {
        ((uint2*)g_q_hi)[i - n4m] = hp;
        ((uint2*)g_q_lo)[i - n4m] = lp;
    }
}

// ---------------- kernel 1: center of spatial_weights ----------------
__global__ void k_center(const float* __restrict__ sw) {
    __shared__ float s0[128], s1[128];
    int i = threadIdx.x;
    float a = 0.f, b = 0.f;
    for (int j = i; j < H_; j += 128) { a += sw[j * 2]; b += sw[j * 2 + 1]; }
    s0[i] = a; s1[i] = b;
    __syncthreads();
    for (int off = 64; off > 0; off >>= 1) {
        if (i < off) { s0[i] += s0[i + off]; s1[i] += s1[i + off]; }
        __syncthreads();
    }
    if (i == 0) { g_center[0] = s0[0] / (float)H_; g_center[1] = s1[0] / (float)H_; }
}

// ---------------- kernel 2: per-row stats ----------------
__global__ void k_prep(const float* __restrict__ query,
                       const float* __restrict__ mem,
                       const float* __restrict__ coords) {
    int w = (blockIdx.x * blockDim.x + threadIdx.x) >> 5;
    int lane = threadIdx.x & 31;
    if (w < M_) {
        const float* row = mem + (size_t)w * D_;
        float ss = 0.f;
        #pragma unroll
        for (int j = 0; j < D_ / 32; j++) { float v = row[lane + j * 32]; ss += v * v; }
        #pragma unroll
        for (int o = 16; o; o >>= 1) ss += __shfl_xor_sync(0xffffffffu, ss, o);
        if (lane == 0) {
            float dx = coords[2 * w]     - g_center[0];
            float dy = coords[2 * w + 1] - g_center[1];
            float2 ra;
            ra.x = 1.f / sqrtf(ss);
            ra.y = 1.f / (1.f + sqrtf(dx * dx + dy * dy));
            g_ra[w] = ra;
        }
    } else if (w < M_ + B_) {
        int b = w - M_;
        const float* row = query + (size_t)b * D_;
        float ss = 0.f;
        #pragma unroll
        for (int j = 0; j < D_ / 32; j++) { float v = row[lane + j * 32]; ss += v * v; }
        #pragma unroll
        for (int o = 16; o; o >>= 1) ss += __shfl_xor_sync(0xffffffffu, ss, o);
        if (lane == 0) g_rq[b] = 1.f / sqrtf(ss);
    }
}

// ---------------- kernel 3: tensor-core GEMM + register top-5 ----------------
__global__ void __launch_bounds__(256, 1) k_main() {
    extern __shared__ char smbuf[];
    uint32_t sbase;
    {
        uint64_t tmp = __cvta_generic_to_shared(smbuf);
        sbase = (uint32_t)tmp;
    }

    int tid = threadIdx.x;
    int lane = tid & 31;
    int wid = tid >> 5;
    int wq = (wid >> 2) * 32;       // 0 or 32
    int wm = (wid & 3) * 64;        // 0,64,128,192
    int qb = blockIdx.y * BQ;
    int mg0 = blockIdx.x * MCH;

    // resident Q hi/lo (swizzled: 16B chunk c of row r goes to chunk (c&~7)|((c^r)&7))
    for (int i = tid; i < BQ * 48; i += 256) {
        int r = i / 48;
        int c = i - r * 48;
        int cs = (c & ~7) | ((c ^ r) & 7);
        *(uint4*)(smbuf + r * 768 + cs * 16) = ((const uint4*)(g_q_hi + (qb + r) * D_))[c];
        *(uint4*)(smbuf + SM_QLO + r * 768 + cs * 16) = ((const uint4*)(g_q_lo + (qb + r) * D_))[c];
    }

    float rq[4];
    #pragma unroll
    for (int l = 0; l < 4; l++)
        rq[l] = g_rq[qb + wq + (l >> 1) * 16 + (l & 1) * 8 + (lane >> 2)];

    float tv[4][K_];
    int   tix[4][K_];
    #pragma unroll
    for (int l = 0; l < 4; l++) {
        #pragma unroll
        for (int s = 0; s < K_; s++) { tv[l][s] = -3.4e38f; tix[l][s] = 0; }
    }

    __syncthreads();

    // initial prefetch: tile 0, stage 0 -> buf 0
    {
        const __half* bh_g = g_mem_hi + (size_t)mg0 * D_;
        const __half* bl_g = g_mem_lo + (size_t)mg0 * D_;
        uint32_t dst = sbase + SM_B;
        #pragma unroll
        for (int l = 0; l < 8; l++) {
            int i = tid + l * 256;
            int r = i >> 3;
            int seg = i & 7;
            uint32_t doff = (uint32_t)(r * 128 + (((seg ^ r) & 7) << 4));
            size_t goff = (size_t)r * D_ + seg * 8;
            CP_ASYNC16(dst + doff, (const void*)(bh_g + goff));
            CP_ASYNC16(dst + BHALF + doff, (const void*)(bl_g + goff));
        }
        CP_COMMIT();
    }

    for (int t = 0; t < NT_; t++) {
        int mg = mg0 + t * BN;

        float acc[2][8][4];
        #pragma unroll
        for (int a = 0; a < 2; a++) {
            #pragma unroll
            for (int b = 0; b < 8; b++) {
                #pragma unroll
                for (int c = 0; c < 4; c++) acc[a][b][c] = 0.f;
            }
        }

        #pragma unroll
        for (int s = 0; s < 6; s++) {
            bool issue = (s < 5) || (t + 1 < NT_);
            if (issue) {
                int kc, mnext;
                uint32_t dst;
                if (s < 5) { kc = (s + 1) * BK; mnext = mg; dst = sbase + SM_B + (uint32_t)(((s + 1) & 1) * BSTG); }
                else       { kc = 0; mnext = mg + BN; dst = sbase + SM_B; }
                const __half* bh_g = g_mem_hi + (size_t)mnext * D_;
                const __half* bl_g = g_mem_lo + (size_t)mnext * D_;
                #pragma unroll
                for (int l = 0; l < 8; l++) {
                    int i = tid + l * 256;
                    int r = i >> 3;
                    int seg = i & 7;
                    uint32_t doff = (uint32_t)(r * 128 + (((seg ^ r) & 7) << 4));
                    size_t goff = (size_t)r * D_ + kc + seg * 8;
                    CP_ASYNC16(dst + doff, (const void*)(bh_g + goff));
                    CP_ASYNC16(dst + BHALF + doff, (const void*)(bl_g + goff));
                }
                CP_COMMIT();
                CP_WAIT1();
            } else {
                CP_WAIT0();
            }
            __syncthreads();

            uint32_t bbuf = sbase + SM_B + (uint32_t)((s & 1) * BSTG);
            #pragma unroll
            for (int ks = 0; ks < 4; ks++) {
                int c16 = s * 8 + ks * 2 + (lane >> 4);
                uint32_t ah[2][4], al[2][4];
                #pragma unroll
                for (int mt = 0; mt < 2; mt++) {
                    int qrow = wq + mt * 16 + (lane & 15);
                    int cs = (c16 & ~7) | ((c16 ^ qrow) & 7);
                    uint32_t aoff = (uint32_t)(qrow * 768 + cs * 16);
                    LDM4(ah[mt][0], ah[mt][1], ah[mt][2], ah[mt][3], sbase + aoff);
                    LDM4(al[mt][0], al[mt][1], al[mt][2], al[mt][3], sbase + SM_QLO + aoff);
                }
                uint32_t bhf[8][2], blf[8][2];
                #pragma unroll
                for (int p = 0; p < 4; p++) {
                    int n = wm + p * 16 + ((lane >> 4) << 3) + (lane & 7);
                    int cb = ks * 2 + ((lane >> 3) & 1);
                    uint32_t boff = (uint32_t)(n * 128 + (((cb ^ n) & 7) << 4));
                    uint32_t r0, r1, r2, r3;
                    LDM4(r0, r1, r2, r3, bbuf + boff);
                    bhf[2 * p][0] = r0; bhf[2 * p][1] = r1;
                    bhf[2 * p + 1][0] = r2; bhf[2 * p + 1][1] = r3;
                    LDM4(r0, r1, r2, r3, bbuf + BHALF + boff);
                    blf[2 * p][0] = r0; blf[2 * p][1] = r1;
                    blf[2 * p + 1][0] = r2; blf[2 * p + 1][1] = r3;
                }
                // pass 1: hi*hi — 16 independent accumulators
                #pragma unroll
                for (int mt = 0; mt < 2; mt++) {
                    #pragma unroll
                    for (int nt = 0; nt < 8; nt++) {
                        MMA16816(acc[mt][nt][0], acc[mt][nt][1], acc[mt][nt][2], acc[mt][nt][3],
                                 ah[mt][0], ah[mt][1], ah[mt][2], ah[mt][3],
                                 bhf[nt][0], bhf[nt][1]);
                    }
                }
                // pass 2: lo*hi
                #pragma unroll
                for (int mt = 0; mt < 2; mt++) {
                    #pragma unroll
                    for (int nt = 0; nt < 8; nt++) {
                        MMA16816(acc[mt][nt][0], acc[mt][nt][1], acc[mt][nt][2], acc[mt][nt][3],
                                 al[mt][0], al[mt][1], al[mt][2], al[mt][3],
                                 bhf[nt][0], bhf[nt][1]);
                    }
                }
                // pass 3: hi*lo
                #pragma unroll
                for (int mt = 0; mt < 2; mt++) {
                    #pragma unroll
                    for (int nt = 0; nt < 8; nt++) {
                        MMA16816(acc[mt][nt][0], acc[mt][nt][1], acc[mt][nt][2], acc[mt][nt][3],
                                 ah[mt][0], ah[mt][1], ah[mt][2], ah[mt][3],
                                 blf[nt][0], blf[nt][1]);
                    }
                }
            }
            __syncthreads();
        }

        // register epilogue: scale + spatial act + top-5 insert (no smem)
        #pragma unroll
        for (int mt = 0; mt < 2; mt++) {
            #pragma unroll
            for (int nt = 0; nt < 8; nt++) {
                int m0 = mg + wm + nt * 8 + 2 * (lane & 3);
                float4 rr4 = *(const float4*)(&g_ra[m0]);   // rm0, act0, rm1, act1
                #pragma unroll
                for (int c = 0; c < 4; c++) {
                    int lst = mt * 2 + (c >> 1);
                    float rm  = (c & 1) ? rr4.z : rr4.x;
                    float act = (c & 1) ? rr4.w : rr4.y;
                    float v = fmaf(acc[mt][nt][c], fminf(rq[lst] * rm, 1e8f), act);
                    if (v > tv[lst][K_ - 1]) {
                        float cv = v;
                        int ci = m0 + (c & 1);
                        #pragma unroll
                        for (int s = 0; s < K_; s++) {
                            bool gt = cv > tv[lst][s];
                            float ov = tv[lst][s]; int oi = tix[lst][s];
                            tv[lst][s]  = gt ? cv : ov;
                            tix[lst][s] = gt ? ci : oi;
                            cv = gt ? ov : cv;
                            ci = gt ? oi : ci;
                        }
                    }
                }
            }
        }
    }

    // final merge via smem (aliases Q region)
    __syncthreads();
    float* mv = (float*)smbuf;
    int*   mi = (int*)(smbuf + 20480);
    int slot = (wid & 3) * 4 + (lane & 3);
    #pragma unroll
    for (int l = 0; l < 4; l++) {
        int q = wq + (l >> 1) * 16 + (l & 1) * 8 + (lane >> 2);
        #pragma unroll
        for (int s = 0; s < K_; s++) {
            mv[(q * 16 + slot) * K_ + s] = tv[l][s];
            mi[(q * 16 + slot) * K_ + s] = tix[l][s];
        }
    }
    __syncthreads();
    if (tid < BQ) {
        float bv[K_];
        int bi[K_];
        #pragma unroll
        for (int s = 0; s < K_; s++) { bv[s] = -3.4e38f; bi[s] = 0; }
        #pragma unroll 4
        for (int c = 0; c < 16 * K_; c++) {
            float v = mv[tid * 80 + c];
            int  ix = mi[tid * 80 + c];
            if (v > bv[K_ - 1]) {
                float cv = v;
                int ci = ix;
                #pragma unroll
                for (int s = 0; s < K_; s++) {
                    bool gt = cv > bv[s];
                    float ov = bv[s]; int oi = bi[s];
                    bv[s] = gt ? cv : ov;
                    bi[s] = gt ? ci : oi;
                    cv = gt ? ov : cv;
                    ci = gt ? oi : ci;
                }
            }
        }
        int b = qb + tid;
        #pragma unroll
        for (int s = 0; s < K_; s++) {
            g_candv[b * (CH_ * K_) + blockIdx.x * K_ + s] = bv[s];
            g_candi[b * (CH_ * K_) + blockIdx.x * K_ + s] = bi[s];
        }
    }
}

// ---------------- kernel 4: merge chunks -> final top-5 ----------------
__global__ void k_topkfinal() {
    int b = blockIdx.x * blockDim.x + threadIdx.x;
    if (b >= B_) return;
    float bv[K_];
    int bi[K_];
    #pragma unroll
    for (int s = 0; s < K_; s++) { bv[s] = -3.4e38f; bi[s] = 0; }
    for (int c = 0; c < CH_ * K_; c++) {
        float v = g_candv[b * (CH_ * K_) + c];
        int  ix = g_candi[b * (CH_ * K_) + c];
        if (v > bv[K_ - 1]) {
            float cv = v;
            int ci = ix;
            #pragma unroll
            for (int s = 0; s < K_; s++) {
                bool gt = cv > bv[s];
                float ov = bv[s]; int oi = bi[s];
                bv[s] = gt ? cv : ov;
                bi[s] = gt ? ci : oi;
                cv = gt ? ov : cv;
                ci = gt ? oi : ci;
            }
        }
    }
    #pragma unroll
    for (int s = 0; s < K_; s++) g_topk[b * K_ + s] = bi[s];
}

// ---------------- kernel 5: tiled GEMM (xproj rows + gate rows in one grid) ----------------
__global__ void __launch_bounds__(256)
k_gemm(const float* __restrict__ W_ih, const float* __restrict__ b_ih,
       const float* __restrict__ W_g, const float* __restrict__ b_g,
       const float* __restrict__ query, const float* __restrict__ mem) {
    __shared__ __align__(16) float a_s[KC * QTP];
    __shared__ __align__(16) float w_s[KC * MTP];
    int tid = threadIdx.x;
    int tx = tid & 15, ty = tid >> 4;
    int mode = (blockIdx.x < 6 * B_ / GBM) ? 0 : 1;
    int rb = (mode == 0) ? blockIdx.x * GBM : (blockIdx.x - 6 * B_ / GBM) * GBM;
    int hb = blockIdx.y * GBN;
    const float* W = (mode == 0) ? W_ih : W_g;
    const float* bias = (mode == 0) ? b_ih : b_g;

    float acc[4][8];
    #pragma unroll
    for (int i = 0; i < 4; i++) {
        #pragma unroll
        for (int j = 0; j < 8; j++) acc[i][j] = 0.f;
    }

    for (int kc = 0; kc < D_; kc += KC) {
        __syncthreads();
        #pragma unroll
        for (int l = 0; l < 2; l++) {
            int idx = tid + l * 256;
            int row = idx >> 3, k4 = idx & 7;
            int r = rb + row;
            const float* src;
            if (mode == 0) {
                int bq = r / 6;
                int tt = r - bq * 6;
                if (tt == 0) src = query + (size_t)bq * D_;
                else src = mem + (size_t)g_topk[bq * K_ + tt - 1] * D_;
            } else {
                src = query + (size_t)r * D_;
            }
            float4 v = *(const float4*)(src + kc + k4 * 4);
            int kl = k4 * 4;
            a_s[(kl + 0) * QTP + row] = v.x;
            a_s[(kl + 1) * QTP + row] = v.y;
            a_s[(kl + 2) * QTP + row] = v.z;
            a_s[(kl + 3) * QTP + row] = v.w;
        }
        #pragma unroll
        for (int l = 0; l < 4; l++) {
            int idx = tid + l * 256;
            int h = idx >> 3, k4 = idx & 7;
            float4 v = *(const float4*)(W + (size_t)(hb + h) * D_ + kc + k4 * 4);
            int kl = k4 * 4;
            w_s[(kl + 0) * MTP + h] = v.x;
            w_s[(kl + 1) * MTP + h] = v.y;
            w_s[(kl + 2) * MTP + h] = v.z;
            w_s[(kl + 3) * MTP + h] = v.w;
        }
        __syncthreads();

        #pragma unroll 8
        for (int k = 0; k < KC; k++) {
            float4 av  = *(const float4*)(a_s + k * QTP + ty * 4);
            float4 b0v = *(const float4*)(w_s + k * MTP + tx * 8);
            float4 b1v = *(const float4*)(w_s + k * MTP + tx * 8 + 4);
            float a[4];
            a[0] = av.x; a[1] = av.y; a[2] = av.z; a[3] = av.w;
            float bb[8];
            bb[0] = b0v.x; bb[1] = b0v.y; bb[2] = b0v.z; bb[3] = b0v.w;
            bb[4] = b1v.x; bb[5] = b1v.y; bb[6] = b1v.z; bb[7] = b1v.w;
            #pragma unroll
            for (int i = 0; i < 4; i++) {
                #pragma unroll
                for (int j = 0; j < 8; j++) acc[i][j] = fmaf(a[i], bb[j], acc[i][j]);
            }
        }
    }

    float* out = (mode == 0) ? g_xproj : g_gate;
    #pragma unroll
    for (int i = 0; i < 4; i++) {
        int r = rb + ty * 4 + i;
        #pragma unroll
        for (int j = 0; j < 8; j++) {
            int h = hb + tx * 8 + j;
            float v = acc[i][j] + bias[h];
            if (mode == 1) v = 1.f / (1.f + expf(-v));
            out[r * H_ + h] = v;
        }
    }
}

// ---------------- kernel 6: fused RNN (step0 + 5 steps + gated mix) ----------------
__global__ void __launch_bounds__(256) k_rnn(const float* __restrict__ Whh,
                                             const float* __restrict__ bhh,
                                             float* __restrict__ out) {
    extern __shared__ float rs[];
    float* h_s = rs;                  // 8 rows * 384
    float* w_s = rs + 8 * H_;         // 384 * RNS (w_s[h][kk])
    int tid = threadIdx.x;
    int r0 = blockIdx.x * 8;

    int rr[12], hh[12];
    #pragma unroll
    for (int o = 0; o < 12; o++) {
        int idx = o * 256 + tid;
        rr[o] = idx / H_;
        hh[o] = idx - rr[o] * H_;
    }

    // step 0: h = tanh(x0 + b_hh)
    #pragma unroll
    for (int o = 0; o < 12; o++)
        h_s[rr[o] * H_ + hh[o]] = tanhf(g_xproj[(r0 + rr[o]) * (6 * H_) + hh[o]] + bhh[hh[o]]);
    __syncthreads();

    for (int t = 1; t <= 5; t++) {
        float hn[12];
        #pragma unroll
        for (int o = 0; o < 12; o++)
            hn[o] = g_xproj[(r0 + rr[o]) * (6 * H_) + t * H_ + hh[o]] + bhh[hh[o]];

        for (int k0 = 0; k0 < H_; k0 += 32) {
            __syncthreads();
            for (int i = tid; i < 32 * H_; i += 256) {
                int kk = i & 31;
                int h = i >> 5;
                w_s[h * RNS + kk] = Whh[h * H_ + k0 + kk];
            }
            __syncthreads();
            #pragma unroll
            for (int o = 0; o < 12; o++) {
                const float4* wp = (const float4*)(w_s + hh[o] * RNS);
                const float4* hp = (const float4*)(h_s + rr[o] * H_ + k0);
                float a = 0.f;
                #pragma unroll
                for (int k4 = 0; k4 < 8; k4++) {
                    float4 w4 = wp[k4];
                    float4 h4 = hp[k4];
                    a = fmaf(w4.x, h4.x, a);
                    a = fmaf(w4.y, h4.y, a);
                    a = fmaf(w4.z, h4.z, a);
                    a = fmaf(w4.w, h4.w, a);
                }
                hn[o] += a;
            }
        }
        __syncthreads();
        if (t < 5) {
            #pragma unroll
            for (int o = 0; o < 12; o++) h_s[rr[o] * H_ + hh[o]] = tanhf(hn[o]);
            __syncthreads();
        } else {
            #pragma unroll
            for (int o = 0; o < 12; o++) {
                int gi = (r0 + rr[o]) * H_ + hh[o];
                float g = g_gate[gi];
                float direct = g_xproj[(r0 + rr[o]) * (6 * H_) + hh[o]];
                out[gi] = g * tanhf(hn[o]) + (1.f - g) * direct;
            }
        }
    }
}

// ---------------- launch ----------------
extern "C" void kernel_launch(void* const* d_in, const int* in_sizes, int n_in,
                              void* d_out, int out_size) {
    const float* query  = (const float*)d_in[0];
    const float* mem    = (const float*)d_in[1];
    const float* coords = (const float*)d_in[2];
    const float* sw     = (const float*)d_in[3];
    const float* W_ih   = (const float*)d_in[4];
    const float* b_ih   = (const float*)d_in[5];
    const float* W_hh   = (const float*)d_in[6];
    const float* b_hh   = (const float*)d_in[7];
    const float* W_g    = (const float*)d_in[8];
    const float* b_g    = (const float*)d_in[9];
    float* out = (float*)d_out;

    int nsplit = (M_ * D_ + B_ * D_) / 4;
    k_split<<<(nsplit + 255) / 256, 256>>>(query, mem);
    k_center<<<1, 128>>>(sw);
    k_prep<<<(M_ + B_) / 8, 256>>>(query, mem, coords);

    cudaFuncSetAttribute(k_main, cudaFuncAttributeMaxDynamicSharedMemorySize, SM_TOT);
    k_main<<<dim3(CH_, B_ / BQ), 256, SM_TOT>>>();

    k_topkfinal<<<32, 32>>>();

    k_gemm<<<dim3(6 * B_ / GBM + B_ / GBM, H_ / GBN), 256>>>(W_ih, b_ih, W_g, b_g, query, mem);

    int rnn_smem = (8 * H_ + H_ * RNS) * 4;
    cudaFuncSetAttribute(k_rnn, cudaFuncAttributeMaxDynamicSharedMemorySize, rnn_smem);
    k_rnn<<<B_ / 8, 256, rnn_smem>>>(W_hh, b_hh, out);
}